// round 14
// baseline (speedup 1.0000x reference)
#include <cuda_runtime.h>
#include <cstdint>

// Lanczos upsample (4,2,256,256) f32 -> (4,2,2048,2048) f32, 8x per axis.
//
// Algebra (validated, rel_err ~1.4e-7): reference nearest-gather + 9-tap
// LUT-Lanczos collapses to a 2x2 weighted gather with 8 compile-time phase
// weight pairs per axis; reflect padding == clamp to boundary source pixel.
//
// Round 14: persistent single-wave kernel. R10's 4096 blocks each end in an
// exposed 32KB drain-wait tail. Now 444 blocks (3/SM, exactly one wave) loop
// over all 4096 four-row spans with TWO alternating 32KB smem buffers:
// compute span i+1 while the engine drains span i's commit; buffer reuse
// gated by wait_group.read 1. Tails collapse 4096 -> 444; engines stay fed.
// evict_first retained (R10-proven).

namespace lw {

constexpr double PI = 3.14159265358979323846;

constexpr double csin(double x) {
    double k = x / (2.0 * PI);
    long long n = (long long)(k >= 0.0 ? k + 0.5 : k - 0.5);
    double r = x - (double)n * (2.0 * PI);
    if (r > PI * 0.5)       r =  PI - r;
    else if (r < -PI * 0.5) r = -PI - r;
    double term = r, sum = r;
    const double r2 = r * r;
    for (int i = 1; i <= 11; ++i) {
        term *= -r2 / ((2.0 * i) * (2.0 * i + 1.0));
        sum += term;
    }
    return sum;
}

constexpr double tap(double d, int p) {
    double t  = d + (double)(p - 4);
    double tp = t * PI;
    double tq = tp * 0.25;
    return (csin(tp) / tp) * (csin(tq) / tq);
}

constexpr float wA(int f) {
    double d = 1e-8 + (double)f / 8.0;
    int r = (f + 4) & 7;
    double a = 0.0;
    for (int p = 0; p < 8 - r; ++p) a += tap(d, p);
    return (float)a;
}
constexpr float wB(int f) {
    double d = 1e-8 + (double)f / 8.0;
    int r = (f + 4) & 7;
    double b = 0.0;
    for (int p = 8 - r; p <= 8; ++p) b += tap(d, p);
    return (float)b;
}

} // namespace lw

// Scalar host constexprs fold into device code as literals (proven pattern).
constexpr float A0 = lw::wA(0), A1 = lw::wA(1), A2 = lw::wA(2), A3 = lw::wA(3);
constexpr float A4 = lw::wA(4), A5 = lw::wA(5), A6 = lw::wA(6), A7 = lw::wA(7);
constexpr float B0 = lw::wB(0), B1 = lw::wB(1), B2 = lw::wB(2), B3 = lw::wB(3);
constexpr float B4 = lw::wB(4), B5 = lw::wB(5), B6 = lw::wB(6), B7 = lw::wB(7);

template <int F> __device__ __forceinline__ constexpr float getA() {
    if constexpr (F == 0) return A0; else if constexpr (F == 1) return A1;
    else if constexpr (F == 2) return A2; else if constexpr (F == 3) return A3;
    else if constexpr (F == 4) return A4; else if constexpr (F == 5) return A5;
    else if constexpr (F == 6) return A6; else return A7;
}
template <int F> __device__ __forceinline__ constexpr float getB() {
    if constexpr (F == 0) return B0; else if constexpr (F == 1) return B1;
    else if constexpr (F == 2) return B2; else if constexpr (F == 3) return B3;
    else if constexpr (F == 4) return B4; else if constexpr (F == 5) return B5;
    else if constexpr (F == 6) return B6; else return B7;
}

__device__ __forceinline__ uint32_t smem_u32(const void* p) {
    uint32_t a;
    asm("{ .reg .u64 t; cvta.to.shared.u64 t, %1; cvt.u32.u64 %0, t; }"
        : "=r"(a) : "l"(p));
    return a;
}

// Compute row at y-phase FY (compile time) into smem. x-phases 0..3 use
// source cols (k-1,k); 4..7 use (k,k+1).
template <int FY>
__device__ __forceinline__ void compute_row(
    float* __restrict__ srow, int k,
    float s00, float s01, float s02, float s10, float s11, float s12)
{
    constexpr float Ay = getA<FY>();
    constexpr float By = getB<FY>();

    const float v0 = Ay * s00 + By * s10;
    const float v1 = Ay * s01 + By * s11;
    const float v2 = Ay * s02 + By * s12;

    float4 o0, o1;
    o0.x = A0 * v0 + B0 * v1;
    o0.y = A1 * v0 + B1 * v1;
    o0.z = A2 * v0 + B2 * v1;
    o0.w = A3 * v0 + B3 * v1;
    o1.x = A4 * v1 + B4 * v2;
    o1.y = A5 * v1 + B5 * v2;
    o1.z = A6 * v1 + B6 * v2;
    o1.w = A7 * v1 + B7 * v2;

    float4* sp = reinterpret_cast<float4*>(srow + k * 8);
    sp[0] = o0;
    sp[1] = o1;
}

__device__ __forceinline__ void bulk_commit32k(const float* sbuf, float* gdst) {
    // Caller guarantees a preceding __syncthreads; thread 0 only.
    asm volatile("fence.proxy.async.shared::cta;" ::: "memory");
    unsigned long long policy;
    asm volatile("createpolicy.fractional.L2::evict_first.b64 %0, 1.0;"
                 : "=l"(policy));
    asm volatile(
        "cp.async.bulk.global.shared::cta.bulk_group.L2::cache_hint"
        " [%0], [%1], %2, %3;"
        :: "l"((unsigned long long)gdst), "r"(smem_u32(sbuf)),
           "n"(32768), "l"(policy) : "memory");
    asm volatile("cp.async.bulk.commit_group;" ::: "memory");
}

// 4096 work items: w = bc*512 + m; span m covers output rows 4m..4m+3 of
// channel bc, blending source rows ry0=clamp((4m-4)>>3), ry1=ry0+1 clamped.
// Thread k owns output columns 8k..8k+7 from source columns k-1,k,k+1.
__device__ __forceinline__ void do_span(
    const float* __restrict__ img, float* __restrict__ out,
    float* __restrict__ sbuf, int w, int k, int km, int kp, bool t0)
{
    const int bc = w >> 9;
    const int m  = w & 511;

    const int y0   = 4 * m;
    const int ry0u = (y0 - 4) >> 3;
    const int ry0  = max(ry0u, 0);
    const int ry1  = min(ry0u + 1, 255);

    const float* __restrict__ base = img + (size_t)bc * 65536;
    const float* __restrict__ r0   = base + ry0 * 256;
    const float* __restrict__ r1   = base + ry1 * 256;

    const float s00 = __ldg(r0 + km), s01 = __ldg(r0 + k), s02 = __ldg(r0 + kp);
    const float s10 = __ldg(r1 + km), s11 = __ldg(r1 + k), s12 = __ldg(r1 + kp);

    if (m & 1) {   // y-phases 4..7
        compute_row<4>(sbuf,            k, s00, s01, s02, s10, s11, s12);
        compute_row<5>(sbuf + 2048,     k, s00, s01, s02, s10, s11, s12);
        compute_row<6>(sbuf + 2 * 2048, k, s00, s01, s02, s10, s11, s12);
        compute_row<7>(sbuf + 3 * 2048, k, s00, s01, s02, s10, s11, s12);
    } else {       // y-phases 0..3
        compute_row<0>(sbuf,            k, s00, s01, s02, s10, s11, s12);
        compute_row<1>(sbuf + 2048,     k, s00, s01, s02, s10, s11, s12);
        compute_row<2>(sbuf + 2 * 2048, k, s00, s01, s02, s10, s11, s12);
        compute_row<3>(sbuf + 3 * 2048, k, s00, s01, s02, s10, s11, s12);
    }

    __syncthreads();
    if (t0) {
        float* gdst = out + ((size_t)bc * 2048 + (size_t)y0) * 2048;
        bulk_commit32k(sbuf, gdst);
    }
}

static constexpr int GRID = 444;   // 3 blocks/SM x 148 SMs: one full wave

__global__ void __launch_bounds__(256)
lz_upsample_kernel(const float* __restrict__ img, float* __restrict__ out) {
    extern __shared__ __align__(128) float ring[];   // 2 x 8192 floats = 64 KB

    const int k  = threadIdx.x;
    const int km = max(k - 1, 0);
    const int kp = min(k + 1, 255);
    const bool t0 = (threadIdx.x == 0);

    int it = 0;
    for (int w = blockIdx.x; w < 4096; w += GRID, ++it) {
        float* sbuf = ring + (it & 1) * 8192;
        if (it >= 2) {
            // Buffer reuse: commit (it-2) must be read-complete. At most the
            // most recent commit may remain pending.
            if (t0) asm volatile("cp.async.bulk.wait_group.read 1;" ::: "memory");
            __syncthreads();   // publish drain to all threads before STS
        }
        do_span(img, out, sbuf, w, k, km, kp, t0);
        // do_span ends with __syncthreads + thread0 commit; next iteration's
        // wait/sync gates reuse, so no extra barrier needed here.
    }

    // Block must not exit while the engine still reads its smem.
    if (t0) asm volatile("cp.async.bulk.wait_group.read 0;" ::: "memory");
}

extern "C" void kernel_launch(void* const* d_in, const int* in_sizes, int n_in,
                              void* d_out, int out_size) {
    (void)in_sizes; (void)n_in; (void)out_size;
    const float* img = (const float*)d_in[0];
    float* out = (float*)d_out;

    // Capture-safe (host attribute set; not a stream op, no allocation).
    cudaFuncSetAttribute(lz_upsample_kernel,
                         cudaFuncAttributeMaxDynamicSharedMemorySize, 65536);

    lz_upsample_kernel<<<GRID, 256, 65536>>>(img, out);
}

// round 15
// speedup vs baseline: 1.0522x; 1.0522x over previous
#include <cuda_runtime.h>
#include <cstdint>

// Lanczos upsample (4,2,256,256) f32 -> (4,2,2048,2048) f32, 8x per axis.
//
// Algebra (validated, rel_err ~1.4e-7): reference nearest-gather + 9-tap
// LUT-Lanczos collapses to a 2x2 weighted gather with 8 compile-time phase
// weight pairs per axis; reflect padding == clamp to boundary source pixel.
//
// Round 15: 8-row blocks, ONE 64KB bulk store per block (vs R11's two 32KB
// commits). Halves bulk-engine commands to 2048, removes the intermediate
// sync/commit boundary, restores evict_first (R10-proven). Independent
// blocks (persistent R14 regressed; concurrency > intra-block pipelining).
// Kernel family is at the ~6 TB/s LTS-ingress write floor; this harvests
// the last command-overhead margin.

namespace lw {

constexpr double PI = 3.14159265358979323846;

constexpr double csin(double x) {
    double k = x / (2.0 * PI);
    long long n = (long long)(k >= 0.0 ? k + 0.5 : k - 0.5);
    double r = x - (double)n * (2.0 * PI);
    if (r > PI * 0.5)       r =  PI - r;
    else if (r < -PI * 0.5) r = -PI - r;
    double term = r, sum = r;
    const double r2 = r * r;
    for (int i = 1; i <= 11; ++i) {
        term *= -r2 / ((2.0 * i) * (2.0 * i + 1.0));
        sum += term;
    }
    return sum;
}

constexpr double tap(double d, int p) {
    double t  = d + (double)(p - 4);
    double tp = t * PI;
    double tq = tp * 0.25;
    return (csin(tp) / tp) * (csin(tq) / tq);
}

constexpr float wA(int f) {
    double d = 1e-8 + (double)f / 8.0;
    int r = (f + 4) & 7;
    double a = 0.0;
    for (int p = 0; p < 8 - r; ++p) a += tap(d, p);
    return (float)a;
}
constexpr float wB(int f) {
    double d = 1e-8 + (double)f / 8.0;
    int r = (f + 4) & 7;
    double b = 0.0;
    for (int p = 8 - r; p <= 8; ++p) b += tap(d, p);
    return (float)b;
}

} // namespace lw

// Scalar host constexprs fold into device code as literals (proven pattern).
constexpr float A0 = lw::wA(0), A1 = lw::wA(1), A2 = lw::wA(2), A3 = lw::wA(3);
constexpr float A4 = lw::wA(4), A5 = lw::wA(5), A6 = lw::wA(6), A7 = lw::wA(7);
constexpr float B0 = lw::wB(0), B1 = lw::wB(1), B2 = lw::wB(2), B3 = lw::wB(3);
constexpr float B4 = lw::wB(4), B5 = lw::wB(5), B6 = lw::wB(6), B7 = lw::wB(7);

template <int F> __device__ __forceinline__ constexpr float getA() {
    if constexpr (F == 0) return A0; else if constexpr (F == 1) return A1;
    else if constexpr (F == 2) return A2; else if constexpr (F == 3) return A3;
    else if constexpr (F == 4) return A4; else if constexpr (F == 5) return A5;
    else if constexpr (F == 6) return A6; else return A7;
}
template <int F> __device__ __forceinline__ constexpr float getB() {
    if constexpr (F == 0) return B0; else if constexpr (F == 1) return B1;
    else if constexpr (F == 2) return B2; else if constexpr (F == 3) return B3;
    else if constexpr (F == 4) return B4; else if constexpr (F == 5) return B5;
    else if constexpr (F == 6) return B6; else return B7;
}

__device__ __forceinline__ uint32_t smem_u32(const void* p) {
    uint32_t a;
    asm("{ .reg .u64 t; cvta.to.shared.u64 t, %1; cvt.u32.u64 %0, t; }"
        : "=r"(a) : "l"(p));
    return a;
}

// Compute row at y-phase FY (compile time) into smem. x-phases 0..3 use
// source cols (k-1,k); 4..7 use (k,k+1).
template <int FY>
__device__ __forceinline__ void compute_row(
    float* __restrict__ srow, int k,
    float s00, float s01, float s02, float s10, float s11, float s12)
{
    constexpr float Ay = getA<FY>();
    constexpr float By = getB<FY>();

    const float v0 = Ay * s00 + By * s10;
    const float v1 = Ay * s01 + By * s11;
    const float v2 = Ay * s02 + By * s12;

    float4 o0, o1;
    o0.x = A0 * v0 + B0 * v1;
    o0.y = A1 * v0 + B1 * v1;
    o0.z = A2 * v0 + B2 * v1;
    o0.w = A3 * v0 + B3 * v1;
    o1.x = A4 * v1 + B4 * v2;
    o1.y = A5 * v1 + B5 * v2;
    o1.z = A6 * v1 + B6 * v2;
    o1.w = A7 * v1 + B7 * v2;

    float4* sp = reinterpret_cast<float4*>(srow + k * 8);
    sp[0] = o0;
    sp[1] = o1;
}

// Grid: 8 channels x 256 eight-row groups. Block (bc,g) emits output rows
// y = 8g..8g+7: phases 0..3 blend source rows (g-1,g) clamped, phases 4..7
// blend (g,g+1) clamped. Thread k owns output columns 8k..8k+7 from source
// columns k-1,k,k+1. All 8 rows staged in 64KB smem, ONE 64KB bulk store.
__global__ void __launch_bounds__(256)
lz_upsample_kernel(const float* __restrict__ img, float* __restrict__ out) {
    extern __shared__ __align__(128) float buf[];   // 16384 floats = 64 KB

    const int b  = blockIdx.x;
    const int bc = b >> 8;
    const int g  = b & 255;

    const int ra = max(g - 1, 0);
    const int rc = min(g + 1, 255);

    const float* __restrict__ base = img + (size_t)bc * 65536;
    const float* __restrict__ pa = base + ra * 256;
    const float* __restrict__ pb = base + g  * 256;
    const float* __restrict__ pc = base + rc * 256;

    const int k  = threadIdx.x;
    const int km = max(k - 1, 0);
    const int kp = min(k + 1, 255);

    const float a0 = __ldg(pa + km), a1 = __ldg(pa + k), a2 = __ldg(pa + kp);
    const float b0 = __ldg(pb + km), b1 = __ldg(pb + k), b2 = __ldg(pb + kp);
    const float c0 = __ldg(pc + km), c1 = __ldg(pc + k), c2 = __ldg(pc + kp);

    // Rows 8g+0..8g+3: phases 0..3, source pair (a,b).
    compute_row<0>(buf,            k, a0, a1, a2, b0, b1, b2);
    compute_row<1>(buf + 2048,     k, a0, a1, a2, b0, b1, b2);
    compute_row<2>(buf + 2 * 2048, k, a0, a1, a2, b0, b1, b2);
    compute_row<3>(buf + 3 * 2048, k, a0, a1, a2, b0, b1, b2);
    // Rows 8g+4..8g+7: phases 4..7, source pair (b,c).
    compute_row<4>(buf + 4 * 2048, k, b0, b1, b2, c0, c1, c2);
    compute_row<5>(buf + 5 * 2048, k, b0, b1, b2, c0, c1, c2);
    compute_row<6>(buf + 6 * 2048, k, b0, b1, b2, c0, c1, c2);
    compute_row<7>(buf + 7 * 2048, k, b0, b1, b2, c0, c1, c2);

    __syncthreads();

    if (threadIdx.x == 0) {
        // Order generic-proxy STS before the async-proxy bulk read.
        asm volatile("fence.proxy.async.shared::cta;" ::: "memory");
        const unsigned long long gdst = (unsigned long long)
            (out + ((size_t)bc * 2048 + (size_t)(8 * g)) * 2048);
        const uint32_t ssrc = smem_u32(buf);
        // evict_first: output never re-read; drain dirty lines eagerly.
        unsigned long long policy;
        asm volatile("createpolicy.fractional.L2::evict_first.b64 %0, 1.0;"
                     : "=l"(policy));
        asm volatile(
            "cp.async.bulk.global.shared::cta.bulk_group.L2::cache_hint"
            " [%0], [%1], %2, %3;"
            :: "l"(gdst), "r"(ssrc), "n"(65536), "l"(policy) : "memory");
        asm volatile("cp.async.bulk.commit_group;" ::: "memory");
        // Block must not exit until the engine has READ the smem buffer.
        asm volatile("cp.async.bulk.wait_group.read 0;" ::: "memory");
    }
}

extern "C" void kernel_launch(void* const* d_in, const int* in_sizes, int n_in,
                              void* d_out, int out_size) {
    (void)in_sizes; (void)n_in; (void)out_size;
    const float* img = (const float*)d_in[0];
    float* out = (float*)d_out;

    // Capture-safe (host attribute set; not a stream op, no allocation).
    cudaFuncSetAttribute(lz_upsample_kernel,
                         cudaFuncAttributeMaxDynamicSharedMemorySize, 65536);

    lz_upsample_kernel<<<8 * 256, 256, 65536>>>(img, out);
}